// round 4
// baseline (speedup 1.0000x reference)
#include <cuda_runtime.h>
#include <math.h>

#define Bb 16
#define Qd 2048
#define Kd 2048
#define Fd 128
#define QT 64
#define KT 64
#define NT 256
#define LSTR 132   // padded row stride (floats) for Q/K/V tiles
#define SSTR 65    // padded row stride for S/D tiles

#define SMEM_FLOATS (3*QT*LSTR + 2*QT*SSTR + QT*2 + KT*2 + 3*QT)
#define SMEM_BYTES (SMEM_FLOATS * 4)

extern __shared__ float sm[];

__global__ void __launch_bounds__(NT, 1) alibi_attn_kernel(
    const float* __restrict__ q, const float* __restrict__ k, const float* __restrict__ v,
    const float* __restrict__ cq, const float* __restrict__ ck,
    const int* __restrict__ am, const int* __restrict__ alm,
    const float* __restrict__ bias_scale, const float* __restrict__ running_mean,
    float* __restrict__ out)
{
    const int b  = blockIdx.y;
    const int q0 = blockIdx.x * QT;
    const int tid = threadIdx.x;

    float* Qs = sm;
    float* Ks = Qs + QT*LSTR;
    float* Vs = Ks + KT*LSTR;
    float* SE = Vs + KT*LSTR;
    float* DD = SE + QT*SSTR;
    float* CQ = DD + QT*SSTR;
    float* CK = CQ + QT*2;
    float* MR = CK + KT*2;
    float* LR = MR + QT;
    float* RS = LR + QT;

    const float dscale = bias_scale[0] / running_mean[0];
    const float sscale = rsqrtf((float)Fd);

    // ---- load Q tile (once) ----
    {
        const float* qbase = q + ((size_t)b*Qd + q0)*Fd;
        #pragma unroll
        for (int it = 0; it < (QT*Fd/4)/NT; it++) {
            int i = tid + it*NT;
            int row = i >> 5;       // Fd/4 = 32 float4 per row
            int c4  = i & 31;
            float4 t = *(const float4*)(qbase + row*Fd + c4*4);
            *(float4*)(Qs + row*LSTR + c4*4) = t;
        }
        if (tid < QT) {
            CQ[tid*2+0] = cq[((size_t)b*Qd + q0 + tid)*2 + 0];
            CQ[tid*2+1] = cq[((size_t)b*Qd + q0 + tid)*2 + 1];
            MR[tid] = -INFINITY;
            LR[tid] = 0.f;
        }
    }

    // phase-B output mapping: 8 q-rows x 4 f-cols per thread
    const int bq0 = (tid >> 5) * 8;
    const int bf0 = (tid & 31) * 4;
    float acc1[8][4], acc2[8][4];
    #pragma unroll
    for (int i = 0; i < 8; i++)
        #pragma unroll
        for (int c = 0; c < 4; c++) { acc1[i][c] = 0.f; acc2[i][c] = 0.f; }

    // phase-A S mapping: 4x4 micro-tile per thread
    const int aq0 = (tid >> 4) * 4;
    const int ak0 = (tid & 15) * 4;

    __syncthreads();

    for (int k0 = 0; k0 < Kd; k0 += KT) {
        // ---- load K/V tiles ----
        {
            const float* kbase = k + ((size_t)b*Kd + k0)*Fd;
            const float* vbase = v + ((size_t)b*Kd + k0)*Fd;
            #pragma unroll
            for (int it = 0; it < (KT*Fd/4)/NT; it++) {
                int i = tid + it*NT;
                int row = i >> 5;
                int c4  = i & 31;
                *(float4*)(Ks + row*LSTR + c4*4) = *(const float4*)(kbase + row*Fd + c4*4);
                *(float4*)(Vs + row*LSTR + c4*4) = *(const float4*)(vbase + row*Fd + c4*4);
            }
            if (tid < KT) {
                CK[tid*2+0] = ck[((size_t)b*Kd + k0 + tid)*2 + 0];
                CK[tid*2+1] = ck[((size_t)b*Kd + k0 + tid)*2 + 1];
            }
        }
        __syncthreads();

        // ---- phase A: S = (Q Kt)*scale, D = masked distances ----
        {
            float s[4][4];
            #pragma unroll
            for (int i = 0; i < 4; i++)
                #pragma unroll
                for (int j = 0; j < 4; j++) s[i][j] = 0.f;

            #pragma unroll 4
            for (int f = 0; f < Fd; f += 4) {
                float4 a[4], bb[4];
                #pragma unroll
                for (int i = 0; i < 4; i++) a[i]  = *(const float4*)(Qs + (aq0+i)*LSTR + f);
                #pragma unroll
                for (int j = 0; j < 4; j++) bb[j] = *(const float4*)(Ks + (ak0+j)*LSTR + f);
                #pragma unroll
                for (int i = 0; i < 4; i++)
                    #pragma unroll
                    for (int j = 0; j < 4; j++) {
                        s[i][j] += a[i].x*bb[j].x;
                        s[i][j] += a[i].y*bb[j].y;
                        s[i][j] += a[i].z*bb[j].z;
                        s[i][j] += a[i].w*bb[j].w;
                    }
            }

            #pragma unroll
            for (int i = 0; i < 4; i++) {
                size_t mbase = ((size_t)b*Qd + q0 + aq0 + i)*(size_t)Kd + k0 + ak0;
                int4 a4 = *(const int4*)(am  + mbase);   // masks are int32 (0/1)
                int4 l4 = *(const int4*)(alm + mbase);
                int av[4] = {a4.x, a4.y, a4.z, a4.w};
                int lv[4] = {l4.x, l4.y, l4.z, l4.w};
                float cqx = CQ[(aq0+i)*2+0], cqy = CQ[(aq0+i)*2+1];
                #pragma unroll
                for (int j = 0; j < 4; j++) {
                    float dx = cqx - CK[(ak0+j)*2+0];
                    float dy = cqy - CK[(ak0+j)*2+1];
                    float dist = sqrtf(dx*dx + dy*dy) * dscale;
                    float dv = lv[j] ? 0.f : dist;          // alibi mask -> 0
                    dv = av[j] ? -1.f : dv;                  // attn mask encoded as sign
                    SE[(aq0+i)*SSTR + ak0 + j] = s[i][j] * sscale;
                    DD[(aq0+i)*SSTR + ak0 + j] = dv;
                }
            }
        }
        __syncthreads();

        // ---- phase A2: online softmax row update (4 threads / row) ----
        {
            int r   = tid >> 2;
            int sub = tid & 3;
            float mloc = -INFINITY;
            #pragma unroll
            for (int j = 0; j < 16; j++)
                mloc = fmaxf(mloc, SE[r*SSTR + sub*16 + j]);
            mloc = fmaxf(mloc, __shfl_xor_sync(0xffffffffu, mloc, 1));
            mloc = fmaxf(mloc, __shfl_xor_sync(0xffffffffu, mloc, 2));

            float mold = MR[r];
            float mnew = fmaxf(mold, mloc);

            float esum = 0.f;
            #pragma unroll
            for (int j = 0; j < 16; j++) {
                int idx = r*SSTR + sub*16 + j;
                float e = __expf(SE[idx] - mnew);   // l sums over ALL k (pre-mask softmax)
                esum += e;
                float dv = DD[idx];
                SE[idx] = (dv < 0.f) ? 0.f : e;      // attn-masked -> numerator excluded
                DD[idx] = fmaxf(dv, 0.f);            // restore masked distance
            }
            esum += __shfl_xor_sync(0xffffffffu, esum, 1);
            esum += __shfl_xor_sync(0xffffffffu, esum, 2);

            if (sub == 0) {
                float rsf = (mold == -INFINITY) ? 0.f : __expf(mold - mnew);
                MR[r] = mnew;
                LR[r] = LR[r]*rsf + esum;
                RS[r] = rsf;
            }
        }
        __syncthreads();

        // ---- phase B: acc1 += E @ V ; acc2 += D @ V ----
        {
            #pragma unroll
            for (int i = 0; i < 8; i++) {
                float rsf = RS[bq0 + i];
                #pragma unroll
                for (int c = 0; c < 4; c++) acc1[i][c] *= rsf;
            }
            #pragma unroll 4
            for (int kk = 0; kk < KT; kk++) {
                float4 v4 = *(const float4*)(Vs + kk*LSTR + bf0);
                #pragma unroll
                for (int i = 0; i < 8; i++) {
                    float e = SE[(bq0+i)*SSTR + kk];
                    float d = DD[(bq0+i)*SSTR + kk];
                    acc1[i][0] += e*v4.x; acc1[i][1] += e*v4.y;
                    acc1[i][2] += e*v4.z; acc1[i][3] += e*v4.w;
                    acc2[i][0] += d*v4.x; acc2[i][1] += d*v4.y;
                    acc2[i][2] += d*v4.z; acc2[i][3] += d*v4.w;
                }
            }
        }
        __syncthreads();
    }

    // ---- epilogue: O = acc1/l - acc2 ----
    #pragma unroll
    for (int i = 0; i < 8; i++) {
        float invl = 1.f / LR[bq0 + i];
        float4 o;
        o.x = acc1[i][0]*invl - acc2[i][0];
        o.y = acc1[i][1]*invl - acc2[i][1];
        o.z = acc1[i][2]*invl - acc2[i][2];
        o.w = acc1[i][3]*invl - acc2[i][3];
        *(float4*)(out + ((size_t)b*Qd + q0 + bq0 + i)*Fd + bf0) = o;
    }
}

extern "C" void kernel_launch(void* const* d_in, const int* in_sizes, int n_in,
                              void* d_out, int out_size) {
    const float* q   = (const float*)d_in[0];
    const float* k   = (const float*)d_in[1];
    const float* v   = (const float*)d_in[2];
    const float* cq  = (const float*)d_in[3];
    const float* ck  = (const float*)d_in[4];
    const int* am    = (const int*)d_in[5];
    const int* alm   = (const int*)d_in[6];
    const float* bs  = (const float*)d_in[7];
    const float* rm  = (const float*)d_in[8];
    float* out = (float*)d_out;

    cudaFuncSetAttribute(alibi_attn_kernel,
                         cudaFuncAttributeMaxDynamicSharedMemorySize, SMEM_BYTES);

    dim3 grid(Qd/QT, Bb);
    alibi_attn_kernel<<<grid, NT, SMEM_BYTES>>>(q, k, v, cq, ck, am, alm, bs, rm, out);
}

// round 6
// speedup vs baseline: 3.6519x; 3.6519x over previous
#include <cuda_runtime.h>
#include <cuda_bf16.h>
#include <stdint.h>

#define Bb 16
#define Qd 2048
#define Kd 2048
#define Fd 128
#define KT 64
#define NT 256

// smem word offsets (uint32 words)
#define W_QS   0                    // [128][68]
#define W_KS   (128*68)             // [64][68]
#define W_VHI  (W_KS + 64*68)       // [32][136]
#define W_VLO  (W_VHI + 32*136)     // [32][136]
#define SMEM_WORDS (W_VLO + 32*136)
#define SMEM_BYTES (SMEM_WORDS*4)

#define PACKBF2(r, lo, hi) asm("cvt.rn.bf16x2.f32 %0, %1, %2;" : "=r"(r) : "f"(hi), "f"(lo))
#define EX2(d, x) asm("ex2.approx.f32 %0, %1;" : "=f"(d) : "f"(x))
#define SQRTA(d, x) asm("sqrt.approx.f32 %0, %1;" : "=f"(d) : "f"(x))

__device__ __forceinline__ void mma16816(float& c0, float& c1, float& c2, float& c3,
                                         uint32_t a0, uint32_t a1, uint32_t a2, uint32_t a3,
                                         uint32_t b0, uint32_t b1) {
    asm volatile("mma.sync.aligned.m16n8k16.row.col.f32.bf16.bf16.f32 "
        "{%0,%1,%2,%3}, {%4,%5,%6,%7}, {%8,%9}, {%0,%1,%2,%3};"
        : "+f"(c0), "+f"(c1), "+f"(c2), "+f"(c3)
        : "r"(a0), "r"(a1), "r"(a2), "r"(a3), "r"(b0), "r"(b1));
}

extern __shared__ uint32_t smw[];

__global__ void __launch_bounds__(NT, 1) alibi_wmma_kernel(
    const float* __restrict__ q, const float* __restrict__ k, const float* __restrict__ v,
    const float* __restrict__ cq, const float* __restrict__ ck,
    const int* __restrict__ am, const int* __restrict__ alm,
    const float* __restrict__ bias_scale, const float* __restrict__ running_mean,
    float* __restrict__ out)
{
    const int b = blockIdx.y, q0 = blockIdx.x * 128;
    const int tid = threadIdx.x;
    const int wid = tid >> 5, lane = tid & 31;
    const int gid = lane >> 2, tig = lane & 3;

    uint32_t* QS  = smw + W_QS;
    uint32_t* KS  = smw + W_KS;
    uint32_t* VHI = smw + W_VHI;
    uint32_t* VLO = smw + W_VLO;

    const float dscale = bias_scale[0] / running_mean[0];
    const float C1 = 0.12753859788f;   // log2(e)/sqrt(128)
    const float C0 = -23.0831206f;     // -16*log2(e)

    // ---- fill Q tile (once): bf16 words [row][68] ----
    {
        const float* qp = q + ((size_t)b * Qd + q0) * Fd;
        #pragma unroll
        for (int it = 0; it < 32; it++) {
            int widx = tid + it * 256;
            int row = widx >> 6, w = widx & 63;
            float2 t = *(const float2*)(qp + row * Fd + 2 * w);
            uint32_t pw; PACKBF2(pw, t.x, t.y);
            QS[row * 68 + w] = pw;
        }
    }

    // per-thread row state
    const int r0l = wid * 16 + gid;                 // local q row (and +8)
    const size_t r0g = (size_t)b * Qd + q0 + r0l;
    const size_t r1g = r0g + 8;
    const float cqx0 = cq[2 * r0g], cqy0 = cq[2 * r0g + 1];
    const float cqx1 = cq[2 * r1g], cqy1 = cq[2 * r1g + 1];
    const size_t m0 = r0g * (size_t)Kd, m1 = r1g * (size_t)Kd;

    float acc1[16][4], acc2[16][4];
    #pragma unroll
    for (int jn = 0; jn < 16; jn++)
        #pragma unroll
        for (int c = 0; c < 4; c++) { acc1[jn][c] = 0.f; acc2[jn][c] = 0.f; }
    float lsum0 = 0.f, lsum1 = 0.f;

    const int qb = r0l * 68 + tig;

    for (int t = 0; t < 32; t++) {
        const int k0 = t * KT;

        // ---- fill K tile: [64][68] ----
        {
            const float* kp = k + ((size_t)b * Kd + k0) * Fd;
            #pragma unroll
            for (int it = 0; it < 16; it++) {
                int widx = tid + it * 256;
                int row = widx >> 6, w = widx & 63;
                float2 tt = *(const float2*)(kp + row * Fd + 2 * w);
                uint32_t pw; PACKBF2(pw, tt.x, tt.y);
                KS[row * 68 + w] = pw;
            }
        }
        // ---- fill V transposed hi/lo: VT[kw][f], stride 136, paired 64-bit stores ----
        {
            const float* vp = v + ((size_t)b * Kd + k0) * Fd;
            #pragma unroll
            for (int it = 0; it < 8; it++) {
                int idx = tid + it * 256;
                int fp = idx & 63, kw = idx >> 6;
                const float* va = vp + (size_t)(2 * kw) * Fd + 2 * fp;
                float2 a = *(const float2*)(va);
                float2 bb = *(const float2*)(va + Fd);
                uint32_t ph0, ph1;
                PACKBF2(ph0, a.x, bb.x);
                PACKBF2(ph1, a.y, bb.y);
                float r0 = a.x  - __uint_as_float(ph0 << 16);
                float r1 = bb.x - __uint_as_float(ph0 & 0xffff0000u);
                float r2 = a.y  - __uint_as_float(ph1 << 16);
                float r3 = bb.y - __uint_as_float(ph1 & 0xffff0000u);
                uint32_t pl0, pl1;
                PACKBF2(pl0, r0, r1);
                PACKBF2(pl1, r2, r3);
                int base = kw * 136 + 2 * fp;
                *(uint2*)(VHI + base) = make_uint2(ph0, ph1);
                *(uint2*)(VLO + base) = make_uint2(pl0, pl1);
            }
        }
        __syncthreads();

        // ---- S = Q @ K^T (per warp: 16 x 64) ----
        float sc[8][4];
        #pragma unroll
        for (int j = 0; j < 8; j++)
            #pragma unroll
            for (int c = 0; c < 4; c++) sc[j][c] = 0.f;

        #pragma unroll
        for (int ks = 0; ks < 8; ks++) {
            uint32_t a0 = QS[qb + 8 * ks];
            uint32_t a1 = QS[qb + 8 * 68 + 8 * ks];
            uint32_t a2 = QS[qb + 8 * ks + 4];
            uint32_t a3 = QS[qb + 8 * 68 + 8 * ks + 4];
            #pragma unroll
            for (int j = 0; j < 8; j++) {
                int kb = (8 * j + gid) * 68 + tig + 8 * ks;
                mma16816(sc[j][0], sc[j][1], sc[j][2], sc[j][3],
                         a0, a1, a2, a3, KS[kb], KS[kb + 4]);
            }
        }

        // ---- elementwise: exp, distance, masks -> bf16 A-fragments ----
        uint32_t Ew0[8], Ew1[8], Hw0[8], Hw1[8], Lw0[8], Lw1[8];
        #pragma unroll
        for (int j = 0; j < 8; j++) {
            int c0 = k0 + j * 8 + tig * 2;
            float4 ckv = *(const float4*)(ck + ((size_t)b * Kd + c0) * 2);
            int2 a0m = *(const int2*)(am  + m0 + c0);
            int2 a1m = *(const int2*)(am  + m1 + c0);
            int2 l0m = *(const int2*)(alm + m0 + c0);
            int2 l1m = *(const int2*)(alm + m1 + c0);

            float e00, e01, e10, e11;
            EX2(e00, fmaf(sc[j][0], C1, C0));
            EX2(e01, fmaf(sc[j][1], C1, C0));
            EX2(e10, fmaf(sc[j][2], C1, C0));
            EX2(e11, fmaf(sc[j][3], C1, C0));
            lsum0 += e00 + e01;
            lsum1 += e10 + e11;

            float dxa = cqx0 - ckv.x, dya = cqy0 - ckv.y;
            float dxb = cqx0 - ckv.z, dyb = cqy0 - ckv.w;
            float dxc = cqx1 - ckv.x, dyc = cqy1 - ckv.y;
            float dxd = cqx1 - ckv.z, dyd = cqy1 - ckv.w;
            float d00, d01, d10, d11;
            SQRTA(d00, fmaf(dxa, dxa, dya * dya));
            SQRTA(d01, fmaf(dxb, dxb, dyb * dyb));
            SQRTA(d10, fmaf(dxc, dxc, dyc * dyc));
            SQRTA(d11, fmaf(dxd, dxd, dyd * dyd));
            d00 *= dscale; d01 *= dscale; d10 *= dscale; d11 *= dscale;

            d00 = (a0m.x | l0m.x) ? 0.f : d00;
            d01 = (a0m.y | l0m.y) ? 0.f : d01;
            d10 = (a1m.x | l1m.x) ? 0.f : d10;
            d11 = (a1m.y | l1m.y) ? 0.f : d11;
            float e00m = a0m.x ? 0.f : e00;
            float e01m = a0m.y ? 0.f : e01;
            float e10m = a1m.x ? 0.f : e10;
            float e11m = a1m.y ? 0.f : e11;

            PACKBF2(Ew0[j], e00m, e01m);
            PACKBF2(Ew1[j], e10m, e11m);
            PACKBF2(Hw0[j], d00, d01);
            PACKBF2(Hw1[j], d10, d11);
            float q00 = d00 - __uint_as_float(Hw0[j] << 16);
            float q01 = d01 - __uint_as_float(Hw0[j] & 0xffff0000u);
            float q10 = d10 - __uint_as_float(Hw1[j] << 16);
            float q11 = d11 - __uint_as_float(Hw1[j] & 0xffff0000u);
            PACKBF2(Lw0[j], q00, q01);
            PACKBF2(Lw1[j], q10, q11);
        }

        // ---- PV: acc1 += E@Vhi ; acc2 += Dhi@Vhi + Dhi@Vlo + Dlo@Vhi ----
        #pragma unroll
        for (int jn = 0; jn < 16; jn++) {
            int vb = jn * 8 + gid + tig * 136;
            #pragma unroll
            for (int ks = 0; ks < 4; ks++) {
                int a = vb + ks * 8 * 136;
                uint32_t bh0 = VHI[a], bh1 = VHI[a + 4 * 136];
                uint32_t bl0 = VLO[a], bl1 = VLO[a + 4 * 136];
                mma16816(acc1[jn][0], acc1[jn][1], acc1[jn][2], acc1[jn][3],
                         Ew0[2*ks], Ew1[2*ks], Ew0[2*ks+1], Ew1[2*ks+1], bh0, bh1);
                mma16816(acc2[jn][0], acc2[jn][1], acc2[jn][2], acc2[jn][3],
                         Hw0[2*ks], Hw1[2*ks], Hw0[2*ks+1], Hw1[2*ks+1], bh0, bh1);
                mma16816(acc2[jn][0], acc2[jn][1], acc2[jn][2], acc2[jn][3],
                         Hw0[2*ks], Hw1[2*ks], Hw0[2*ks+1], Hw1[2*ks+1], bl0, bl1);
                mma16816(acc2[jn][0], acc2[jn][1], acc2[jn][2], acc2[jn][3],
                         Lw0[2*ks], Lw1[2*ks], Lw0[2*ks+1], Lw1[2*ks+1], bh0, bh1);
            }
        }
        __syncthreads();
    }

    // ---- epilogue ----
    lsum0 += __shfl_xor_sync(0xffffffffu, lsum0, 1);
    lsum0 += __shfl_xor_sync(0xffffffffu, lsum0, 2);
    lsum1 += __shfl_xor_sync(0xffffffffu, lsum1, 1);
    lsum1 += __shfl_xor_sync(0xffffffffu, lsum1, 2);
    float inv0 = 1.f / lsum0, inv1 = 1.f / lsum1;

    float* o0 = out + r0g * Fd + tig * 2;
    float* o1 = out + r1g * Fd + tig * 2;
    #pragma unroll
    for (int jn = 0; jn < 16; jn++) {
        float2 w0, w1;
        w0.x = acc1[jn][0] * inv0 - acc2[jn][0];
        w0.y = acc1[jn][1] * inv0 - acc2[jn][1];
        w1.x = acc1[jn][2] * inv1 - acc2[jn][2];
        w1.y = acc1[jn][3] * inv1 - acc2[jn][3];
        *(float2*)(o0 + jn * 8) = w0;
        *(float2*)(o1 + jn * 8) = w1;
    }
}

extern "C" void kernel_launch(void* const* d_in, const int* in_sizes, int n_in,
                              void* d_out, int out_size) {
    const float* q   = (const float*)d_in[0];
    const float* k   = (const float*)d_in[1];
    const float* v   = (const float*)d_in[2];
    const float* cq  = (const float*)d_in[3];
    const float* ck  = (const float*)d_in[4];
    const int* am    = (const int*)d_in[5];
    const int* alm   = (const int*)d_in[6];
    const float* bs  = (const float*)d_in[7];
    const float* rm  = (const float*)d_in[8];
    float* out = (float*)d_out;

    cudaFuncSetAttribute(alibi_wmma_kernel,
                         cudaFuncAttributeMaxDynamicSharedMemorySize, SMEM_BYTES);
    dim3 grid(Qd / 128, Bb);
    alibi_wmma_kernel<<<grid, NT, SMEM_BYTES>>>(q, k, v, cq, ck, am, alm, bs, rm, out);
}

// round 7
// speedup vs baseline: 5.9331x; 1.6247x over previous
#include <cuda_runtime.h>
#include <cuda_bf16.h>
#include <stdint.h>

#define Bb 16
#define Qd 2048
#define Kd 2048
#define Fd 128
#define KT 64
#define NT 256

// smem word offsets (uint32 words)
#define W_QS   0                    // [128][68]
#define W_KS   (128*68)             // [64][68]
#define W_VHI  (W_KS + 64*68)       // [32][136]
#define W_VLO  (W_VHI + 32*136)     // [32][136]
#define SMEM_WORDS (W_VLO + 32*136)
#define SMEM_BYTES (SMEM_WORDS*4)
#define SMEM1_BYTES ((128*68 + 64*68)*4)

#define PACKBF2(r, lo, hi) asm("cvt.rn.bf16x2.f32 %0, %1, %2;" : "=r"(r) : "f"(hi), "f"(lo))
#define EX2(d, x) asm("ex2.approx.f32 %0, %1;" : "=f"(d) : "f"(x))
#define SQRTA(d, x) asm("sqrt.approx.f32 %0, %1;" : "=f"(d) : "f"(x))

__device__ float g_lsum[Bb * Qd];

__device__ __forceinline__ void mma16816(float& c0, float& c1, float& c2, float& c3,
                                         uint32_t a0, uint32_t a1, uint32_t a2, uint32_t a3,
                                         uint32_t b0, uint32_t b1) {
    asm volatile("mma.sync.aligned.m16n8k16.row.col.f32.bf16.bf16.f32 "
        "{%0,%1,%2,%3}, {%4,%5,%6,%7}, {%8,%9}, {%0,%1,%2,%3};"
        : "+f"(c0), "+f"(c1), "+f"(c2), "+f"(c3)
        : "r"(a0), "r"(a1), "r"(a2), "r"(a3), "r"(b0), "r"(b1));
}

extern __shared__ uint32_t smw[];

// ---------------- kernel 1: softmax denominators ----------------
__global__ void __launch_bounds__(NT, 1) lsum_kernel(
    const float* __restrict__ q, const float* __restrict__ k)
{
    const int b = blockIdx.y, q0 = blockIdx.x * 128;
    const int tid = threadIdx.x;
    const int wid = tid >> 5, lane = tid & 31;
    const int gid = lane >> 2, tig = lane & 3;

    uint32_t* QS = smw + W_QS;
    uint32_t* KS = smw + W_KS;

    const float C1 = 0.12753859788f;   // log2(e)/sqrt(128)
    const float C0 = -23.0831206f;     // -16*log2(e)

    {
        const float* qp = q + ((size_t)b * Qd + q0) * Fd;
        #pragma unroll
        for (int it = 0; it < 32; it++) {
            int widx = tid + it * 256;
            int row = widx >> 6, w = widx & 63;
            float2 t = *(const float2*)(qp + row * Fd + 2 * w);
            uint32_t pw; PACKBF2(pw, t.x, t.y);
            QS[row * 68 + w] = pw;
        }
    }

    const int r0l = wid * 16 + gid;
    const int qb = r0l * 68 + tig;
    float lsum0 = 0.f, lsum1 = 0.f;

    for (int t = 0; t < 32; t++) {
        const int k0 = t * KT;
        {
            const float* kp = k + ((size_t)b * Kd + k0) * Fd;
            #pragma unroll
            for (int it = 0; it < 16; it++) {
                int widx = tid + it * 256;
                int row = widx >> 6, w = widx & 63;
                float2 tt = *(const float2*)(kp + row * Fd + 2 * w);
                uint32_t pw; PACKBF2(pw, tt.x, tt.y);
                KS[row * 68 + w] = pw;
            }
        }
        __syncthreads();

        float sc[8][4];
        #pragma unroll
        for (int j = 0; j < 8; j++)
            #pragma unroll
            for (int c = 0; c < 4; c++) sc[j][c] = 0.f;

        #pragma unroll
        for (int ks = 0; ks < 8; ks++) {
            uint32_t a0 = QS[qb + 8 * ks];
            uint32_t a1 = QS[qb + 8 * 68 + 8 * ks];
            uint32_t a2 = QS[qb + 8 * ks + 4];
            uint32_t a3 = QS[qb + 8 * 68 + 8 * ks + 4];
            #pragma unroll
            for (int j = 0; j < 8; j++) {
                int kb = (8 * j + gid) * 68 + tig + 8 * ks;
                mma16816(sc[j][0], sc[j][1], sc[j][2], sc[j][3],
                         a0, a1, a2, a3, KS[kb], KS[kb + 4]);
            }
        }
        #pragma unroll
        for (int j = 0; j < 8; j++) {
            float e0, e1, e2, e3;
            EX2(e0, fmaf(sc[j][0], C1, C0));
            EX2(e1, fmaf(sc[j][1], C1, C0));
            EX2(e2, fmaf(sc[j][2], C1, C0));
            EX2(e3, fmaf(sc[j][3], C1, C0));
            lsum0 += e0 + e1;
            lsum1 += e2 + e3;
        }
        __syncthreads();
    }

    lsum0 += __shfl_xor_sync(0xffffffffu, lsum0, 1);
    lsum0 += __shfl_xor_sync(0xffffffffu, lsum0, 2);
    lsum1 += __shfl_xor_sync(0xffffffffu, lsum1, 1);
    lsum1 += __shfl_xor_sync(0xffffffffu, lsum1, 2);
    if (tig == 0) {
        g_lsum[(size_t)b * Qd + q0 + r0l] = lsum0;
        g_lsum[(size_t)b * Qd + q0 + r0l + 8] = lsum1;
    }
}

// ---------------- kernel 2: P = softmax - dist, O = P @ V ----------------
__global__ void __launch_bounds__(NT, 1) alibi_main_kernel(
    const float* __restrict__ q, const float* __restrict__ k, const float* __restrict__ v,
    const float* __restrict__ cq, const float* __restrict__ ck,
    const int* __restrict__ am, const int* __restrict__ alm,
    const float* __restrict__ bias_scale, const float* __restrict__ running_mean,
    float* __restrict__ out)
{
    const int b = blockIdx.y, q0 = blockIdx.x * 128;
    const int tid = threadIdx.x;
    const int wid = tid >> 5, lane = tid & 31;
    const int gid = lane >> 2, tig = lane & 3;

    uint32_t* QS  = smw + W_QS;
    uint32_t* KS  = smw + W_KS;
    uint32_t* VHI = smw + W_VHI;
    uint32_t* VLO = smw + W_VLO;

    const float dscale = bias_scale[0] / running_mean[0];
    const float C1 = 0.12753859788f;
    const float C0 = -23.0831206f;

    {
        const float* qp = q + ((size_t)b * Qd + q0) * Fd;
        #pragma unroll
        for (int it = 0; it < 32; it++) {
            int widx = tid + it * 256;
            int row = widx >> 6, w = widx & 63;
            float2 t = *(const float2*)(qp + row * Fd + 2 * w);
            uint32_t pw; PACKBF2(pw, t.x, t.y);
            QS[row * 68 + w] = pw;
        }
    }

    const int r0l = wid * 16 + gid;
    const size_t r0g = (size_t)b * Qd + q0 + r0l;
    const size_t r1g = r0g + 8;
    const float cqx0 = cq[2 * r0g], cqy0 = cq[2 * r0g + 1];
    const float cqx1 = cq[2 * r1g], cqy1 = cq[2 * r1g + 1];
    const size_t m0 = r0g * (size_t)Kd, m1 = r1g * (size_t)Kd;
    const float inv0 = 1.f / g_lsum[r0g];
    const float inv1 = 1.f / g_lsum[r1g];

    float acc[16][4];
    #pragma unroll
    for (int jn = 0; jn < 16; jn++)
        #pragma unroll
        for (int c = 0; c < 4; c++) acc[jn][c] = 0.f;

    const int qb = r0l * 68 + tig;

    for (int t = 0; t < 32; t++) {
        const int k0 = t * KT;

        {
            const float* kp = k + ((size_t)b * Kd + k0) * Fd;
            #pragma unroll
            for (int it = 0; it < 16; it++) {
                int widx = tid + it * 256;
                int row = widx >> 6, w = widx & 63;
                float2 tt = *(const float2*)(kp + row * Fd + 2 * w);
                uint32_t pw; PACKBF2(pw, tt.x, tt.y);
                KS[row * 68 + w] = pw;
            }
        }
        {
            const float* vp = v + ((size_t)b * Kd + k0) * Fd;
            #pragma unroll
            for (int it = 0; it < 8; it++) {
                int idx = tid + it * 256;
                int fp = idx & 63, kw = idx >> 6;
                const float* va = vp + (size_t)(2 * kw) * Fd + 2 * fp;
                float2 a = *(const float2*)(va);
                float2 bb = *(const float2*)(va + Fd);
                uint32_t ph0, ph1;
                PACKBF2(ph0, a.x, bb.x);
                PACKBF2(ph1, a.y, bb.y);
                float r0 = a.x  - __uint_as_float(ph0 << 16);
                float r1 = bb.x - __uint_as_float(ph0 & 0xffff0000u);
                float r2 = a.y  - __uint_as_float(ph1 << 16);
                float r3 = bb.y - __uint_as_float(ph1 & 0xffff0000u);
                uint32_t pl0, pl1;
                PACKBF2(pl0, r0, r1);
                PACKBF2(pl1, r2, r3);
                int base = kw * 136 + 2 * fp;
                *(uint2*)(VHI + base) = make_uint2(ph0, ph1);
                *(uint2*)(VLO + base) = make_uint2(pl0, pl1);
            }
        }
        __syncthreads();

        // ---- S = Q @ K^T ----
        float sc[8][4];
        #pragma unroll
        for (int j = 0; j < 8; j++)
            #pragma unroll
            for (int c = 0; c < 4; c++) sc[j][c] = 0.f;

        #pragma unroll
        for (int ks = 0; ks < 8; ks++) {
            uint32_t a0 = QS[qb + 8 * ks];
            uint32_t a1 = QS[qb + 8 * 68 + 8 * ks];
            uint32_t a2 = QS[qb + 8 * ks + 4];
            uint32_t a3 = QS[qb + 8 * 68 + 8 * ks + 4];
            #pragma unroll
            for (int j = 0; j < 8; j++) {
                int kb = (8 * j + gid) * 68 + tig + 8 * ks;
                mma16816(sc[j][0], sc[j][1], sc[j][2], sc[j][3],
                         a0, a1, a2, a3, KS[kb], KS[kb + 4]);
            }
        }

        // ---- elementwise: P = (attn?0:e*inv) - (mask?0:dist), split hi/lo ----
        uint32_t Hw0[8], Hw1[8], Lw0[8], Lw1[8];
        #pragma unroll
        for (int j = 0; j < 8; j++) {
            int c0 = k0 + j * 8 + tig * 2;
            float4 ckv = *(const float4*)(ck + ((size_t)b * Kd + c0) * 2);
            int2 a0m = *(const int2*)(am  + m0 + c0);
            int2 a1m = *(const int2*)(am  + m1 + c0);
            int2 l0m = *(const int2*)(alm + m0 + c0);
            int2 l1m = *(const int2*)(alm + m1 + c0);

            float e00, e01, e10, e11;
            EX2(e00, fmaf(sc[j][0], C1, C0));
            EX2(e01, fmaf(sc[j][1], C1, C0));
            EX2(e10, fmaf(sc[j][2], C1, C0));
            EX2(e11, fmaf(sc[j][3], C1, C0));

            float dxa = cqx0 - ckv.x, dya = cqy0 - ckv.y;
            float dxb = cqx0 - ckv.z, dyb = cqy0 - ckv.w;
            float dxc = cqx1 - ckv.x, dyc = cqy1 - ckv.y;
            float dxd = cqx1 - ckv.z, dyd = cqy1 - ckv.w;
            float d00, d01, d10, d11;
            SQRTA(d00, fmaf(dxa, dxa, dya * dya));
            SQRTA(d01, fmaf(dxb, dxb, dyb * dyb));
            SQRTA(d10, fmaf(dxc, dxc, dyc * dyc));
            SQRTA(d11, fmaf(dxd, dxd, dyd * dyd));

            d00 = (a0m.x | l0m.x) ? 0.f : d00 * dscale;
            d01 = (a0m.y | l0m.y) ? 0.f : d01 * dscale;
            d10 = (a1m.x | l1m.x) ? 0.f : d10 * dscale;
            d11 = (a1m.y | l1m.y) ? 0.f : d11 * dscale;

            float p00 = (a0m.x ? 0.f : e00 * inv0) - d00;
            float p01 = (a0m.y ? 0.f : e01 * inv0) - d01;
            float p10 = (a1m.x ? 0.f : e10 * inv1) - d10;
            float p11 = (a1m.y ? 0.f : e11 * inv1) - d11;

            PACKBF2(Hw0[j], p00, p01);
            PACKBF2(Hw1[j], p10, p11);
            float q00 = p00 - __uint_as_float(Hw0[j] << 16);
            float q01 = p01 - __uint_as_float(Hw0[j] & 0xffff0000u);
            float q10 = p10 - __uint_as_float(Hw1[j] << 16);
            float q11 = p11 - __uint_as_float(Hw1[j] & 0xffff0000u);
            PACKBF2(Lw0[j], q00, q01);
            PACKBF2(Lw1[j], q10, q11);
        }

        // ---- acc += Phi@Vhi + Phi@Vlo + Plo@Vhi ----
        #pragma unroll
        for (int jn = 0; jn < 16; jn++) {
            int vb = jn * 8 + gid + tig * 136;
            #pragma unroll
            for (int ks = 0; ks < 4; ks++) {
                int a = vb + ks * 8 * 136;
                uint32_t bh0 = VHI[a], bh1 = VHI[a + 4 * 136];
                uint32_t bl0 = VLO[a], bl1 = VLO[a + 4 * 136];
                mma16816(acc[jn][0], acc[jn][1], acc[jn][2], acc[jn][3],
                         Hw0[2*ks], Hw1[2*ks], Hw0[2*ks+1], Hw1[2*ks+1], bh0, bh1);
                mma16816(acc[jn][0], acc[jn][1], acc[jn][2], acc[jn][3],
                         Hw0[2*ks], Hw1[2*ks], Hw0[2*ks+1], Hw1[2*ks+1], bl0, bl1);
                mma16816(acc[jn][0], acc[jn][1], acc[jn][2], acc[jn][3],
                         Lw0[2*ks], Lw1[2*ks], Lw0[2*ks+1], Lw1[2*ks+1], bh0, bh1);
            }
        }
        __syncthreads();
    }

    float* o0 = out + r0g * Fd + tig * 2;
    float* o1 = out + r1g * Fd + tig * 2;
    #pragma unroll
    for (int jn = 0; jn < 16; jn++) {
        *(float2*)(o0 + jn * 8) = make_float2(acc[jn][0], acc[jn][1]);
        *(float2*)(o1 + jn * 8) = make_float2(acc[jn][2], acc[jn][3]);
    }
}

extern "C" void kernel_launch(void* const* d_in, const int* in_sizes, int n_in,
                              void* d_out, int out_size) {
    const float* q   = (const float*)d_in[0];
    const float* k   = (const float*)d_in[1];
    const float* v   = (const float*)d_in[2];
    const float* cq  = (const float*)d_in[3];
    const float* ck  = (const float*)d_in[4];
    const int* am    = (const int*)d_in[5];
    const int* alm   = (const int*)d_in[6];
    const float* bs  = (const float*)d_in[7];
    const float* rm  = (const float*)d_in[8];
    float* out = (float*)d_out;

    cudaFuncSetAttribute(lsum_kernel,
                         cudaFuncAttributeMaxDynamicSharedMemorySize, SMEM1_BYTES);
    cudaFuncSetAttribute(alibi_main_kernel,
                         cudaFuncAttributeMaxDynamicSharedMemorySize, SMEM_BYTES);

    dim3 grid(Qd / 128, Bb);
    lsum_kernel<<<grid, NT, SMEM1_BYTES>>>(q, k);
    alibi_main_kernel<<<grid, NT, SMEM_BYTES>>>(q, k, v, cq, ck, am, alm, bs, rm, out);
}